// round 4
// baseline (speedup 1.0000x reference)
#include <cuda_runtime.h>
#include <math.h>

#define S_DIM 512
#define B_DIM 32
#define T_DIM 1024
#define E_DIM 512
#define Q_DIM 128
#define SPB   16         // s-rows per block in kernel C
#define TCH   32         // t-chunk (weight tile width)
#define CUT   16.0f      // exponent cutoff: exp(-16) ~ 1.1e-7
#define RPW   8          // rows per warp in kernel A

// Scratch (allocation-free rule: __device__ globals). Layout [B][S].
__device__ float g_mr[B_DIM * S_DIM];    // mean_raw = exp(q.w0 + b0)
__device__ float g_sd[B_DIM * S_DIM];    // std      = exp(q.w1 + b1)
__device__ float g_mean[B_DIM * S_DIM];  // position + cumsum(mean_raw)/20

// Packed f32x2 helpers (Blackwell FFMA2 — only reachable via PTX).
static __device__ __forceinline__ unsigned long long pack2f(float a, float b) {
    unsigned long long r;
    asm("mov.b64 %0, {%1, %2};" : "=l"(r) : "f"(a), "f"(b));
    return r;
}
static __device__ __forceinline__ unsigned long long fma2(
    unsigned long long a, unsigned long long b, unsigned long long c) {
    unsigned long long d;
    asm("fma.rn.f32x2 %0, %1, %2, %3;" : "=l"(d) : "l"(a), "l"(b), "l"(c));
    return d;
}

// ---------------------------------------------------------------------------
// Kernel A: one warp per 8 rows r = s*B+b. Per row: coalesced float4 load +
// dot4 -> 16 per-lane partial sums (8 rows x {d0,d1}). A single multi-value
// butterfly (16 SHFLs total) reduces ALL 16 sums at once: after it, lane L
// holds the total for value index (L>>1)&15. One __expf per lane.
// ---------------------------------------------------------------------------
__global__ void __launch_bounds__(256) ga_qdot(const float* __restrict__ q,
                                               const float* __restrict__ W,
                                               const float* __restrict__ bias) {
    int warp = (blockIdx.x * blockDim.x + threadIdx.x) >> 5;
    int lane = threadIdx.x & 31;
    int r0   = warp * RPW;
    if (r0 >= S_DIM * B_DIM) return;

    float4 a0 = ((const float4*)W)[lane];
    float4 a1 = ((const float4*)W)[32 + lane];

    float v[16];
    #pragma unroll
    for (int k = 0; k < RPW; k++) {
        float4 x = ((const float4*)q)[(size_t)(r0 + k) * 32 + lane];
        v[2 * k]     = x.x * a0.x + x.y * a0.y + x.z * a0.z + x.w * a0.w;
        v[2 * k + 1] = x.x * a1.x + x.y * a1.y + x.z * a1.z + x.w * a1.w;
    }

    // Multi-value butterfly: 16 values -> 1, lane-partitioned.
    #pragma unroll
    for (int i = 0; i < 8; i++) {
        float send = (lane & 16) ? v[i] : v[i + 8];
        float recv = __shfl_xor_sync(0xFFFFFFFFu, send, 16);
        v[i] = ((lane & 16) ? v[i + 8] : v[i]) + recv;
    }
    #pragma unroll
    for (int i = 0; i < 4; i++) {
        float send = (lane & 8) ? v[i] : v[i + 4];
        float recv = __shfl_xor_sync(0xFFFFFFFFu, send, 8);
        v[i] = ((lane & 8) ? v[i + 4] : v[i]) + recv;
    }
    #pragma unroll
    for (int i = 0; i < 2; i++) {
        float send = (lane & 4) ? v[i] : v[i + 2];
        float recv = __shfl_xor_sync(0xFFFFFFFFu, send, 4);
        v[i] = ((lane & 4) ? v[i + 2] : v[i]) + recv;
    }
    {
        float send = (lane & 2) ? v[0] : v[1];
        float recv = __shfl_xor_sync(0xFFFFFFFFu, send, 2);
        v[0] = ((lane & 2) ? v[1] : v[0]) + recv;
    }
    v[0] += __shfl_xor_sync(0xFFFFFFFFu, v[0], 1);

    // lane L holds value m=(L>>1)&15: row k=m>>1, output j=m&1.
    int m = (lane >> 1) & 15;
    int k = m >> 1;
    int j = m & 1;
    float e = __expf(v[0] + bias[j]);
    if (!(lane & 1)) {
        int r = r0 + k;
        int s = r >> 5;      // r / B_DIM
        int b = r & 31;      // r % B_DIM
        if (j == 0) g_mr[b * S_DIM + s] = e;
        else        g_sd[b * S_DIM + s] = e;
    }
}

// ---------------------------------------------------------------------------
// Kernel B: one block per b, 512 threads, shuffle-based inclusive scan.
// ---------------------------------------------------------------------------
__global__ void ga_scan(const float* __restrict__ pos,
                        float* __restrict__ out_mean) {
    int b = blockIdx.x;
    int s = threadIdx.x;           // 512 threads
    int lane = s & 31, wid = s >> 5;
    __shared__ float wsum[16];

    float v = g_mr[b * S_DIM + s];
    #pragma unroll
    for (int off = 1; off < 32; off <<= 1) {
        float y = __shfl_up_sync(0xFFFFFFFFu, v, off);
        if (lane >= off) v += y;
    }
    if (lane == 31) wsum[wid] = v;
    __syncthreads();
    if (wid == 0) {
        float w = (lane < 16) ? wsum[lane] : 0.0f;
        #pragma unroll
        for (int off = 1; off < 16; off <<= 1) {
            float y = __shfl_up_sync(0xFFFFFFFFu, w, off);
            if (lane >= off) w += y;
        }
        if (lane < 16) wsum[lane] = w;
    }
    __syncthreads();
    float base = wid ? wsum[wid - 1] : 0.0f;
    float m = pos[s * B_DIM + b] + (v + base) * 0.05f;
    g_mean[b * S_DIM + s]   = m;
    out_mean[s * B_DIM + b] = m;
}

// ---------------------------------------------------------------------------
// Kernel C: windowed Gaussian attention as a tiny tiled GEMM.
// Block = (SPB=16 s-rows, batch b), 128 threads. Warps 0-1 own si 0-7,
// warps 2-3 own si 8-15. Thread tile: 8 si x 8 e (two float4 slices eA=h*4,
// eB=h*4+256). Each union-window row: 2 coalesced LDG.128 + 8 broadcast
// LDS.64 (packed (w,w)) + 32 fma.rn.f32x2, software-pipelined depth 2.
// ---------------------------------------------------------------------------
__global__ void __launch_bounds__(128) ga_ctx(const float* __restrict__ emb,
                                              const float* __restrict__ mask,
                                              float* __restrict__ out) {
    int b    = blockIdx.y;
    int s0   = blockIdx.x * SPB;
    int tid  = threadIdx.x;
    int half = tid >> 6;          // 0: si 0-7, 1: si 8-15
    int h    = tid & 63;          // thread within half

    __shared__ float smean[SPB];
    __shared__ float sstd[SPB];
    __shared__ unsigned long long sw2[SPB][TCH];   // packed (w,w)

    if (tid < SPB) {
        smean[tid] = g_mean[b * S_DIM + s0 + tid];
        sstd[tid]  = g_sd[b * S_DIM + s0 + tid];
    }
    __syncthreads();

    // Union window over the SPB s-rows (uniform across block).
    int tlo = T_DIM, thi = -1;
    #pragma unroll
    for (int i = 0; i < SPB; i++) {
        float mean = smean[i];
        float hw   = sqrtf(CUT / sstd[i]);
        int lo = (int)fmaxf(0.0f, ceilf(mean - hw));
        int hi = (int)fminf((float)(T_DIM - 1), floorf(mean + hw));
        tlo = min(tlo, lo);
        thi = max(thi, hi);
    }

    ulonglong2 accA[8], accB[8];
    #pragma unroll
    for (int i = 0; i < 8; i++) {
        accA[i].x = accA[i].y = 0ull;
        accB[i].x = accB[i].y = 0ull;
    }

    const int   eA = h * 4;
    const int   eB = h * 4 + 256;
    const size_t rstride = (size_t)B_DIM * E_DIM;

    for (int tb = tlo; tb <= thi; tb += TCH) {
        int n = min(TCH, thi - tb + 1);
        __syncthreads();
        // Fill SPB*TCH = 512 weights: 128 threads x 4.
        #pragma unroll
        for (int i = 0; i < 4; i++) {
            int idx = tid + i * 128;          // 0..511
            int si  = idx >> 5;               // / TCH
            int tj  = idx & (TCH - 1);
            float wv = 0.0f;
            if (tj < n) {
                int   t = tb + tj;
                float d = smean[si] - (float)t;
                wv = __expf(-sstd[si] * d * d) * mask[t * B_DIM + b];
            }
            sw2[si][tj] = pack2f(wv, wv);
        }
        __syncthreads();

        const float* ep = emb + ((size_t)tb * B_DIM + b) * E_DIM;
        ulonglong2 va = *(const ulonglong2*)(ep + eA);   // prefetch row 0
        ulonglong2 vb = *(const ulonglong2*)(ep + eB);
        for (int j = 0; j < n; j++) {
            ep += rstride;
            ulonglong2 na = va, nb = vb;
            if (j + 1 < n) {
                na = *(const ulonglong2*)(ep + eA);      // prefetch next row
                nb = *(const ulonglong2*)(ep + eB);
            }
            #pragma unroll
            for (int r = 0; r < 8; r++) {
                unsigned long long w2 = sw2[half * 8 + r][j];  // broadcast LDS.64
                accA[r].x = fma2(va.x, w2, accA[r].x);
                accA[r].y = fma2(va.y, w2, accA[r].y);
                accB[r].x = fma2(vb.x, w2, accB[r].x);
                accB[r].y = fma2(vb.y, w2, accB[r].y);
            }
            va = na; vb = nb;
        }
    }

    #pragma unroll
    for (int r = 0; r < 8; r++) {
        float* op = out + ((size_t)(s0 + half * 8 + r) * B_DIM + b) * E_DIM;
        *(ulonglong2*)(op + eA) = accA[r];
        *(ulonglong2*)(op + eB) = accB[r];
    }
}

// ---------------------------------------------------------------------------
extern "C" void kernel_launch(void* const* d_in, const int* in_sizes, int n_in,
                              void* d_out, int out_size) {
    const float* query = (const float*)d_in[0];  // [S,B,Q]
    const float* emb   = (const float*)d_in[1];  // [T,B,E]
    const float* mask  = (const float*)d_in[2];  // [T,B]
    const float* pos   = (const float*)d_in[3];  // [S,B]
    const float* W     = (const float*)d_in[4];  // [2,Q]
    const float* bias  = (const float*)d_in[5];  // [2]

    float* out_ctx  = (float*)d_out;                                  // [S,B,E]
    float* out_mean = (float*)d_out + (size_t)S_DIM * B_DIM * E_DIM;  // [S,B]

    // A: 2048 warps (8 rows each), 8 warps/block -> 256 blocks
    ga_qdot<<<(S_DIM * B_DIM) / RPW / 8, 256>>>(query, W, bias);
    // B: one block per batch
    ga_scan<<<B_DIM, S_DIM>>>(pos, out_mean);
    // C: (S/SPB, B) blocks of 128 threads
    dim3 grid(S_DIM / SPB, B_DIM);
    ga_ctx<<<grid, 128>>>(emb, mask, out_ctx);
}

// round 5
// speedup vs baseline: 1.1705x; 1.1705x over previous
#include <cuda_runtime.h>
#include <math.h>

#define S_DIM 512
#define B_DIM 32
#define T_DIM 1024
#define E_DIM 512
#define Q_DIM 128
#define SPB   16         // s-rows per consumer block
#define TCH   16         // t-chunk (weight tile width)
#define CUT   16.0f      // exponent cutoff: exp(-16) ~ 1.1e-7

// Scratch (allocation-free rule: __device__ globals).
__device__ float2 g_ms[B_DIM * S_DIM];   // (mean, std), layout [b][s]
__device__ int    g_flag[B_DIM];         // 0 -> 1 when producer b done (monotone)

// Packed f32x2 helpers (Blackwell FFMA2 — only reachable via PTX).
static __device__ __forceinline__ unsigned long long pack2f(float a, float b) {
    unsigned long long r;
    asm("mov.b64 %0, {%1, %2};" : "=l"(r) : "f"(a), "f"(b));
    return r;
}
static __device__ __forceinline__ unsigned long long fma2(
    unsigned long long a, unsigned long long b, unsigned long long c) {
    unsigned long long d;
    asm("fma.rn.f32x2 %0, %1, %2, %3;" : "=l"(d) : "l"(a), "l"(b), "l"(c));
    return d;
}

// ---------------------------------------------------------------------------
// ONE fused kernel. Grid (B, 1 + S/SPB), 128 threads.
//   blockIdx.y == 0 : producer for batch b — dots + exp + scan, flag release.
//   blockIdx.y >= 1 : consumer chunk (by-1) — windowed Gaussian context GEMM.
// ---------------------------------------------------------------------------
__global__ void __launch_bounds__(128) ga_fused(
    const float* __restrict__ q,     // [S,B,Q]
    const float* __restrict__ emb,   // [T,B,E]
    const float* __restrict__ mask,  // [T,B]
    const float* __restrict__ pos,   // [S,B]
    const float* __restrict__ W,     // [2,Q]
    const float* __restrict__ bias,  // [2]
    float* __restrict__ out_ctx,     // [S,B,E]
    float* __restrict__ out_mean)    // [S,B]
{
    const int b   = blockIdx.x;
    const int tid = threadIdx.x;
    const int warp = tid >> 5;
    const int lane = tid & 31;

    if (blockIdx.y == 0) {
        // ================= PRODUCER =================
        __shared__ float p_mr[S_DIM];
        __shared__ float p_sd[S_DIM];
        __shared__ float wsum[4];

        float4 a0 = ((const float4*)W)[lane];
        float4 a1 = ((const float4*)W)[32 + lane];
        float b0 = bias[0], b1 = bias[1];

        // Warp w owns s in [w*128, w*128+128), groups of 8 rows.
        for (int g = 0; g < 16; g++) {
            int r0 = warp * 128 + g * 8;
            float v[16];
            #pragma unroll
            for (int k = 0; k < 8; k++) {
                int s = r0 + k;
                float4 x = ((const float4*)q)[((size_t)s * B_DIM + b) * 32 + lane];
                v[2 * k]     = x.x * a0.x + x.y * a0.y + x.z * a0.z + x.w * a0.w;
                v[2 * k + 1] = x.x * a1.x + x.y * a1.y + x.z * a1.z + x.w * a1.w;
            }
            // Multi-value butterfly: 16 sums reduced in 16 SHFLs (lane-partitioned).
            #pragma unroll
            for (int i = 0; i < 8; i++) {
                float send = (lane & 16) ? v[i] : v[i + 8];
                float recv = __shfl_xor_sync(0xFFFFFFFFu, send, 16);
                v[i] = ((lane & 16) ? v[i + 8] : v[i]) + recv;
            }
            #pragma unroll
            for (int i = 0; i < 4; i++) {
                float send = (lane & 8) ? v[i] : v[i + 4];
                float recv = __shfl_xor_sync(0xFFFFFFFFu, send, 8);
                v[i] = ((lane & 8) ? v[i + 4] : v[i]) + recv;
            }
            #pragma unroll
            for (int i = 0; i < 2; i++) {
                float send = (lane & 4) ? v[i] : v[i + 2];
                float recv = __shfl_xor_sync(0xFFFFFFFFu, send, 4);
                v[i] = ((lane & 4) ? v[i + 2] : v[i]) + recv;
            }
            {
                float send = (lane & 2) ? v[0] : v[1];
                float recv = __shfl_xor_sync(0xFFFFFFFFu, send, 2);
                v[0] = ((lane & 2) ? v[1] : v[0]) + recv;
            }
            v[0] += __shfl_xor_sync(0xFFFFFFFFu, v[0], 1);

            // lane L holds value m=(L>>1)&15: row k=m>>1, output j=m&1.
            int m = (lane >> 1) & 15;
            int k = m >> 1;
            int j = m & 1;
            float e = __expf(v[0] + (j ? b1 : b0));
            if (!(lane & 1)) {
                if (j == 0) p_mr[r0 + k] = e;
                else        p_sd[r0 + k] = e;
            }
        }
        __syncthreads();

        // Block scan over 512: thread t owns s = 4t..4t+3.
        float a_0 = p_mr[4 * tid + 0];
        float a_1 = p_mr[4 * tid + 1];
        float a_2 = p_mr[4 * tid + 2];
        float a_3 = p_mr[4 * tid + 3];
        float c0 = a_0, c1 = c0 + a_1, c2 = c1 + a_2, c3 = c2 + a_3;
        float tot = c3;
        float tincl = tot;
        #pragma unroll
        for (int off = 1; off < 32; off <<= 1) {
            float y = __shfl_up_sync(0xFFFFFFFFu, tincl, off);
            if (lane >= off) tincl += y;
        }
        if (lane == 31) wsum[warp] = tincl;
        __syncthreads();
        float base = 0.0f;
        #pragma unroll
        for (int w = 0; w < 4; w++) base += (w < warp) ? wsum[w] : 0.0f;
        float excl = base + tincl - tot;

        #pragma unroll
        for (int i = 0; i < 4; i++) {
            int s = 4 * tid + i;
            float ci = (i == 0) ? c0 : (i == 1) ? c1 : (i == 2) ? c2 : c3;
            float mean = pos[(size_t)s * B_DIM + b] + (excl + ci) * 0.05f;
            g_ms[b * S_DIM + s] = make_float2(mean, p_sd[s]);
            out_mean[(size_t)s * B_DIM + b] = mean;
        }
        __syncthreads();
        if (tid == 0) {
            __threadfence();
            asm volatile("st.release.gpu.global.b32 [%0], %1;"
                         :: "l"(&g_flag[b]), "r"(1) : "memory");
        }
        return;
    }

    // ================= CONSUMER =================
    const int s0   = (blockIdx.y - 1) * SPB;
    const int half = tid >> 6;        // 0: si 0-7, 1: si 8-15
    const int h    = tid & 63;

    __shared__ float smean[SPB];
    __shared__ float sstd[SPB];
    __shared__ unsigned long long sw2[SPB][TCH];   // packed (w,w)

    if (tid == 0) {
        int f;
        do {
            asm volatile("ld.acquire.gpu.global.b32 %0, [%1];"
                         : "=r"(f) : "l"(&g_flag[b]) : "memory");
            if (!f) __nanosleep(64);
        } while (!f);
    }
    __syncthreads();

    if (tid < SPB) {
        float2 ms = g_ms[b * S_DIM + s0 + tid];
        smean[tid] = ms.x;
        sstd[tid]  = ms.y;
    }
    __syncthreads();

    // Union window over the SPB s-rows (uniform across block).
    int tlo = T_DIM, thi = -1;
    #pragma unroll
    for (int i = 0; i < SPB; i++) {
        float mean = smean[i];
        float hw   = sqrtf(CUT / sstd[i]);
        int lo = (int)fmaxf(0.0f, ceilf(mean - hw));
        int hi = (int)fminf((float)(T_DIM - 1), floorf(mean + hw));
        tlo = min(tlo, lo);
        thi = max(thi, hi);
    }

    ulonglong2 accA[8], accB[8];
    #pragma unroll
    for (int i = 0; i < 8; i++) {
        accA[i].x = accA[i].y = 0ull;
        accB[i].x = accB[i].y = 0ull;
    }

    const int eA = h * 4;
    const int eB = h * 4 + 256;
    const size_t rstride = (size_t)B_DIM * E_DIM;

    for (int tb = tlo; tb <= thi; tb += TCH) {
        int n = min(TCH, thi - tb + 1);
        __syncthreads();
        // Fill SPB*TCH = 256 weights: 128 threads x 2.
        #pragma unroll
        for (int i = 0; i < 2; i++) {
            int idx = tid + i * 128;          // 0..255
            int si  = idx >> 4;               // / TCH
            int tj  = idx & (TCH - 1);
            float wv = 0.0f;
            if (tj < n) {
                int   t = tb + tj;
                float d = smean[si] - (float)t;
                wv = __expf(-sstd[si] * d * d) * mask[(size_t)t * B_DIM + b];
            }
            sw2[si][tj] = pack2f(wv, wv);
        }
        __syncthreads();

        const float* ep = emb + ((size_t)tb * B_DIM + b) * E_DIM;
        ulonglong2 va = *(const ulonglong2*)(ep + eA);   // prefetch row 0
        ulonglong2 vb = *(const ulonglong2*)(ep + eB);
        for (int j = 0; j < n; j++) {
            ep += rstride;
            ulonglong2 na = va, nb = vb;
            if (j + 1 < n) {
                na = *(const ulonglong2*)(ep + eA);      // prefetch next row
                nb = *(const ulonglong2*)(ep + eB);
            }
            #pragma unroll
            for (int r = 0; r < 8; r++) {
                unsigned long long w2 = sw2[half * 8 + r][j];  // broadcast LDS.64
                accA[r].x = fma2(va.x, w2, accA[r].x);
                accA[r].y = fma2(va.y, w2, accA[r].y);
                accB[r].x = fma2(vb.x, w2, accB[r].x);
                accB[r].y = fma2(vb.y, w2, accB[r].y);
            }
            va = na; vb = nb;
        }
    }

    #pragma unroll
    for (int r = 0; r < 8; r++) {
        float* op = out_ctx + ((size_t)(s0 + half * 8 + r) * B_DIM + b) * E_DIM;
        *(ulonglong2*)(op + eA) = accA[r];
        *(ulonglong2*)(op + eB) = accB[r];
    }
}

// ---------------------------------------------------------------------------
extern "C" void kernel_launch(void* const* d_in, const int* in_sizes, int n_in,
                              void* d_out, int out_size) {
    const float* query = (const float*)d_in[0];  // [S,B,Q]
    const float* emb   = (const float*)d_in[1];  // [T,B,E]
    const float* mask  = (const float*)d_in[2];  // [T,B]
    const float* pos   = (const float*)d_in[3];  // [S,B]
    const float* W     = (const float*)d_in[4];  // [2,Q]
    const float* bias  = (const float*)d_in[5];  // [2]

    float* out_ctx  = (float*)d_out;                                  // [S,B,E]
    float* out_mean = (float*)d_out + (size_t)S_DIM * B_DIM * E_DIM;  // [S,B]

    dim3 grid(B_DIM, 1 + S_DIM / SPB);   // 32 producers first, 1024 consumers
    ga_fused<<<grid, 128>>>(query, emb, mask, pos, W, bias, out_ctx, out_mean);
}